// round 14
// baseline (speedup 1.0000x reference)
#include <cuda_runtime.h>
#include <cuda_bf16.h>
#include <mma.h>
#include <cstdint>

using namespace nvcuda;

// Problem constants
static constexpr int Bb   = 4;
static constexpr int Sseq = 2048;
static constexpr int Eemb = 1024;
static constexpr int Hh   = 16;
static constexpr int Dd   = 64;
static constexpr int Mrows = Bb * Sseq;   // 8192
static constexpr int NBIG  = Mrows * Eemb;   // 8388608
static constexpr int NWGT  = Eemb * Eemb;    // 1048576

// Scratch (device globals: allocation-free)
__device__ float g_q[(size_t)NBIG];    // Q proj (tf32 bits)
__device__ float g_k[(size_t)NBIG];    // K proj TRANSPOSED [b,h][d][s] (tf32)
__device__ float g_v[(size_t)NBIG];    // V proj (tf32 bits)
__device__ float g_o[(size_t)NBIG];    // attn out (tf32 bits)
__device__ float g_cq[(size_t)NBIG];   // input q (tf32 bits)
__device__ float g_ck[(size_t)NBIG];   // input k (tf32 bits)
__device__ float g_cv[(size_t)NBIG];   // input v (tf32 bits)
__device__ float g_wq[(size_t)NWGT];   // weights (tf32 bits)
__device__ float g_wk[(size_t)NWGT];
__device__ float g_wv[(size_t)NWGT];
__device__ float g_wo[(size_t)NWGT];

// ---------------------------------------------------------------------------
// cp.async helpers
// ---------------------------------------------------------------------------
__device__ __forceinline__ void cp_async16(void* smem, const void* gmem) {
    uint32_t s = (uint32_t)__cvta_generic_to_shared(smem);
    asm volatile("cp.async.cg.shared.global [%0], [%1], 16;\n" :: "r"(s), "l"(gmem));
}
__device__ __forceinline__ void cp_commit() {
    asm volatile("cp.async.commit_group;\n");
}
template<int N> __device__ __forceinline__ void cp_wait() {
    asm volatile("cp.async.wait_group %0;\n" :: "n"(N));
}

// ---------------------------------------------------------------------------
// Elementwise fp32 -> tf32-bits converter. grid.y selects array (0..6).
// ---------------------------------------------------------------------------
__global__ __launch_bounds__(256) void cvt_tf32_kernel(
    const float* __restrict__ s0, const float* __restrict__ s1,
    const float* __restrict__ s2, const float* __restrict__ s3,
    const float* __restrict__ s4, const float* __restrict__ s5,
    const float* __restrict__ s6,
    float* __restrict__ d0, float* __restrict__ d1, float* __restrict__ d2,
    float* __restrict__ d3, float* __restrict__ d4, float* __restrict__ d5,
    float* __restrict__ d6)
{
    const int y = blockIdx.y;
    const float* src; float* dst; int n;
    switch (y) {
        case 0: src = s0; dst = d0; n = NBIG; break;
        case 1: src = s1; dst = d1; n = NBIG; break;
        case 2: src = s2; dst = d2; n = NBIG; break;
        case 3: src = s3; dst = d3; n = NWGT; break;
        case 4: src = s4; dst = d4; n = NWGT; break;
        case 5: src = s5; dst = d5; n = NWGT; break;
        default: src = s6; dst = d6; n = NWGT; break;
    }
    const int stride = gridDim.x * blockDim.x * 4;
    for (int i = (blockIdx.x * blockDim.x + threadIdx.x) * 4; i < n; i += stride) {
        float4 v = *(const float4*)(src + i);
        v.x = wmma::__float_to_tf32(v.x);
        v.y = wmma::__float_to_tf32(v.y);
        v.z = wmma::__float_to_tf32(v.z);
        v.w = wmma::__float_to_tf32(v.w);
        *(float4*)(dst + i) = v;
    }
}

// ---------------------------------------------------------------------------
// GEMM: C[M,N] = A[M,K] @ W[K,N] + bias[N]  (M=8192, K=N=1024), tf32 wmma.
// Pre-converted tf32 operands -> zero cvt in mainloop.
// 256 threads, 8 warps of 64x32 tiles (acc = 64 regs/thread -> ~120 regs
// -> 2 CTAs x 256 thr = 16 warps/SM, 2x the latency hiding of the 64x64
// shape). 3-stage cp.async ring, padded smem.
// z==1 && kT: store output TRANSPOSED per head ([b,h][d][s]) for flash's
// conflict-free row-major K fragments. Each 16x16 acc block lies within one
// (b,h) (blocks 16-aligned, head=64-aligned, batch=2048-aligned).
// ---------------------------------------------------------------------------
static constexpr int GBM = 128, GBN = 128, GBK = 32;
static constexpr int LDA = 36;    // GBK + 4
static constexpr int LDB = 132;   // GBN + 4
static constexpr int GSTAGE = GBM * LDA + GBK * LDB;
static constexpr int GEMM_SMEM_BYTES = 3 * GSTAGE * (int)sizeof(float); // 105984

__global__ __launch_bounds__(256, 2) void gemm_bias_kernel(
    const float* __restrict__ A0, const float* __restrict__ A1,
    const float* __restrict__ A2,
    const float* __restrict__ W0, const float* __restrict__ W1,
    const float* __restrict__ W2,
    const float* __restrict__ bias0, const float* __restrict__ bias1,
    const float* __restrict__ bias2,
    float* __restrict__ C0, float* __restrict__ C1, float* __restrict__ C2,
    int cvt_out, int kT)
{
    constexpr int K = 1024, N = 1024;

    const int z = blockIdx.z;
    const float* A    = (z == 0) ? A0 : (z == 1) ? A1 : A2;
    const float* W    = (z == 0) ? W0 : (z == 1) ? W1 : W2;
    const float* bias = (z == 0) ? bias0 : (z == 1) ? bias1 : bias2;
    float*       C    = (z == 0) ? C0 : (z == 1) ? C1 : C2;
    const bool transK = (z == 1) && kT;

    extern __shared__ float smg[];

    const int tid  = threadIdx.x;
    const int lane = tid & 31;
    const int bm   = blockIdx.y * GBM;
    const int bn   = blockIdx.x * GBN;
    const int warp = tid >> 5;          // 0..7
    const int wr   = (warp >> 2) * 64;  // 2 row blocks of 64
    const int wc   = (warp & 3) * 32;   // 4 col blocks of 32

    auto issue_tile = [&](int kt, int buf) {
        const int k0 = kt * GBK;
        float* Ab = smg + buf * GSTAGE;
        float* Bbuf = Ab + GBM * LDA;
        #pragma unroll
        for (int t = 0; t < 4; t++) {
            int lin = tid + t * 256;
            int r = lin >> 3, c4 = lin & 7;
            cp_async16(Ab + r * LDA + c4 * 4,
                       A + (size_t)(bm + r) * K + k0 + c4 * 4);
        }
        #pragma unroll
        for (int t = 0; t < 4; t++) {
            int lin = tid + t * 256;
            int r = lin >> 5, c4 = lin & 31;
            cp_async16(Bbuf + r * LDB + c4 * 4,
                       W + (size_t)(k0 + r) * N + bn + c4 * 4);
        }
    };

    issue_tile(0, 0);
    cp_commit();
    issue_tile(1, 1);
    cp_commit();

    wmma::fragment<wmma::accumulator, 16, 16, 8, float> acc[4][2];
    #pragma unroll
    for (int i = 0; i < 4; i++)
        #pragma unroll
        for (int j = 0; j < 2; j++)
            wmma::fill_fragment(acc[i][j], 0.f);

    const int KT_ = K / GBK;  // 32
    int cur = 0;
    for (int kt = 0; kt < KT_; kt++) {
        if (kt + 1 < KT_) cp_wait<1>(); else cp_wait<0>();
        __syncthreads();
        if (kt + 2 < KT_) {
            int nb = cur + 2; if (nb >= 3) nb -= 3;
            issue_tile(kt + 2, nb);
            cp_commit();
        }

        const float* Ab = smg + cur * GSTAGE;
        const float* Bbuf = Ab + GBM * LDA;

        #pragma unroll
        for (int kk = 0; kk < GBK; kk += 8) {
            wmma::fragment<wmma::matrix_a, 16, 16, 8, wmma::precision::tf32,
                           wmma::row_major> af[4];
            #pragma unroll
            for (int i = 0; i < 4; i++)
                wmma::load_matrix_sync(af[i], Ab + (wr + i * 16) * LDA + kk, LDA);
            #pragma unroll
            for (int j = 0; j < 2; j++) {
                wmma::fragment<wmma::matrix_b, 16, 16, 8, wmma::precision::tf32,
                               wmma::row_major> bf;
                wmma::load_matrix_sync(bf, Bbuf + kk * LDB + wc + j * 16, LDB);
                #pragma unroll
                for (int i = 0; i < 4; i++)
                    wmma::mma_sync(acc[i][j], af[i], bf, acc[i][j]);
            }
        }
        cur++; if (cur == 3) cur = 0;
    }

    // epilogue
    #pragma unroll
    for (int j = 0; j < 2; j++) {
        const int colb = bn + wc + j * 16;
        const int col0 = colb + (lane & 3) * 2;
        float b0 = __ldg(bias + col0);
        float b1 = __ldg(bias + col0 + 1);
        float b8 = __ldg(bias + col0 + 8);
        float b9 = __ldg(bias + col0 + 9);
        #pragma unroll
        for (int i = 0; i < 4; i++) {
            acc[i][j].x[0] += b0; acc[i][j].x[1] += b1;
            acc[i][j].x[2] += b0; acc[i][j].x[3] += b1;
            acc[i][j].x[4] += b8; acc[i][j].x[5] += b9;
            acc[i][j].x[6] += b8; acc[i][j].x[7] += b9;
            if (cvt_out) {
                #pragma unroll
                for (int t = 0; t < 8; t++)
                    acc[i][j].x[t] = wmma::__float_to_tf32(acc[i][j].x[t]);
            }
            const int row0 = bm + wr + i * 16;
            if (transK) {
                // K^T store: element (r,c) -> [(b,h)][d=colb%64+c][s=row0%2048+r]
                const int bIdx = row0 >> 11;         // token / 2048
                const int s    = row0 & 2047;
                const int h    = colb >> 6;
                const int d    = colb & 63;
                float* dst = C + ((size_t)((bIdx << 4) + h) * 64 + d) * Sseq + s;
                wmma::store_matrix_sync(dst, acc[i][j], Sseq, wmma::mem_col_major);
            } else {
                wmma::store_matrix_sync(C + (size_t)row0 * N + colb,
                                        acc[i][j], N, wmma::mem_row_major);
            }
        }
    }
}

// ---------------------------------------------------------------------------
// Causal flash attention, tf32 wmma, Br=64, Bc=64, 4 warps (128 threads),
// software-pipelined (QK[j] -> PV[j-1] -> softmax[j]).
// K arrives TRANSPOSED ([b,h][d][s]) -> QK B-fragments are row_major,
// conflict-free (was col_major stride-68 strided LDS). V row-major as before.
// Q/K/V pre-converted tf32; P converts before store; O written as tf32 bits.
// smem = Q + 2K + 2V + P = 104 KB -> 2 CTAs/SM.
// ---------------------------------------------------------------------------
static constexpr int LDP = 68;
static constexpr int KVTILE = 64 * LDP;
static constexpr int FLASH_SMEM_BYTES =
    (6 * KVTILE) * (int)sizeof(float);         // 104448

__global__ __launch_bounds__(128, 2) void flash_kernel(
    const float* __restrict__ Q, const float* __restrict__ KT,
    const float* __restrict__ V, float* __restrict__ O)
{
    extern __shared__ float sm[];
    float* Qs = sm;
    float* Ks = Qs + KVTILE;           // [2]  (K^T tiles: row = d, col = key)
    float* Vs = Ks + 2 * KVTILE;       // [2]
    float* Ps = Vs + 2 * KVTILE;       // per-warp private 16-row bands

    const int tid  = threadIdx.x;
    const int warp = tid >> 5;
    const int lane = tid & 31;
    const int qt   = (Sseq / 64 - 1) - blockIdx.x;
    const int bh   = blockIdx.y;
    const int b    = bh >> 4;
    const int h    = bh & 15;
    const float scale = 0.125f;        // 1/sqrt(64), power of 2

    const float* qb  = Q + ((size_t)b * Sseq + (size_t)qt * 64) * Eemb + h * Dd;
    const float* kTb = KT + (size_t)bh * 64 * Sseq;   // [d][s]
    const float* vb  = V + (size_t)b * Sseq * Eemb + h * Dd;

    auto issueK = [&](int j, int buf) {
        float* Kd = Ks + buf * KVTILE;
        const float* kt = kTb + (size_t)j * 64;   // col offset
        #pragma unroll
        for (int t = 0; t < 8; t++) {
            int lin = tid + t * 128;
            int r = lin >> 4, c4 = lin & 15;      // r = d row, c4*4 = key col
            cp_async16(Kd + r * LDP + c4 * 4, kt + (size_t)r * Sseq + c4 * 4);
        }
    };
    auto issueV = [&](int j, int buf) {
        const float* vt = vb + (size_t)j * 64 * Eemb;
        float* Vd = Vs + buf * KVTILE;
        #pragma unroll
        for (int t = 0; t < 8; t++) {
            int lin = tid + t * 128;
            int r = lin >> 4, c4 = lin & 15;
            cp_async16(Vd + r * LDP + c4 * 4, vt + (size_t)r * Eemb + c4 * 4);
        }
    };

    issueK(0, 0); cp_commit();
    issueV(0, 0); cp_commit();

    // Q tile: already tf32 bits; scale by 2^-3 (exact)
    #pragma unroll
    for (int t = 0; t < 8; t++) {
        int lin = tid + t * 128;
        int r = lin >> 4, c4 = lin & 15;
        float4 v4 = *(const float4*)(qb + (size_t)r * Eemb + c4 * 4);
        v4.x *= scale; v4.y *= scale; v4.z *= scale; v4.w *= scale;
        *(float4*)(Qs + r * LDP + c4 * 4) = v4;
    }

    float m0 = -1e30f, m1 = -1e30f, l0 = 0.f, l1 = 0.f;

    wmma::fragment<wmma::accumulator, 16, 16, 8, float> oacc[4];
    #pragma unroll
    for (int n = 0; n < 4; n++) wmma::fill_fragment(oacc[n], 0.f);

    const int warp_row0 = warp * 16;
    const int lr0 = warp_row0 + (lane >> 2);
    const int lr1 = lr0 + 8;
    const int nkv = qt + 1;

    auto do_pv = [&](int jj) {
        const float* Vc = Vs + (jj & 1) * KVTILE;
        #pragma unroll
        for (int kk = 0; kk < 64; kk += 8) {
            wmma::fragment<wmma::matrix_a, 16, 16, 8, wmma::precision::tf32,
                           wmma::row_major> af;
            wmma::load_matrix_sync(af, Ps + warp_row0 * LDP + kk, LDP);
            #pragma unroll
            for (int n = 0; n < 4; n++) {
                wmma::fragment<wmma::matrix_b, 16, 16, 8, wmma::precision::tf32,
                               wmma::row_major> bf;
                wmma::load_matrix_sync(bf, Vc + kk * LDP + n * 16, LDP);
                wmma::mma_sync(oacc[n], af, bf, oacc[n]);
            }
        }
    };

    for (int j = 0; j < nkv; j++) {
        const int cur = j & 1;

        cp_wait<1>();
        __syncthreads();  // S1: K[cur] visible; K[cur^1] free
        if (j + 1 < nkv) { issueK(j + 1, cur ^ 1); cp_commit(); }

        // ---- QK[j] ----  B = K^T tile, row_major (rows = d)
        const float* Kc = Ks + cur * KVTILE;
        wmma::fragment<wmma::accumulator, 16, 16, 8, float> sacc[4];
        #pragma unroll
        for (int n = 0; n < 4; n++) wmma::fill_fragment(sacc[n], 0.f);
        #pragma unroll
        for (int kk = 0; kk < 64; kk += 8) {
            wmma::fragment<wmma::matrix_a, 16, 16, 8, wmma::precision::tf32,
                           wmma::row_major> af;
            wmma::load_matrix_sync(af, Qs + warp_row0 * LDP + kk, LDP);
            #pragma unroll
            for (int n = 0; n < 4; n++) {
                wmma::fragment<wmma::matrix_b, 16, 16, 8, wmma::precision::tf32,
                               wmma::row_major> bf;
                wmma::load_matrix_sync(bf, Kc + kk * LDP + n * 16, LDP);
                wmma::mma_sync(sacc[n], af, bf, sacc[n]);
            }
        }

        // ---- PV[j-1] (drains under softmax[j]) ----
        if (j > 0) do_pv(j - 1);

        // ---- softmax[j] ----
        if (j == qt) {
            #pragma unroll
            for (int n = 0; n < 4; n++)
                #pragma unroll
                for (int t = 0; t < 8; t++) {
                    int c  = n * 16 + (lane & 3) * 2 + (t & 1) + ((t & 4) ? 8 : 0);
                    int lr = (t & 2) ? lr1 : lr0;
                    if (c > lr) sacc[n].x[t] = -1e30f;
                }
        }

        float m0n = m0, m1n = m1;
        #pragma unroll
        for (int n = 0; n < 4; n++)
            #pragma unroll
            for (int t = 0; t < 8; t++) {
                if (t & 2) m1n = fmaxf(m1n, sacc[n].x[t]);
                else       m0n = fmaxf(m0n, sacc[n].x[t]);
            }
        m0n = fmaxf(m0n, __shfl_xor_sync(0xffffffffu, m0n, 1));
        m0n = fmaxf(m0n, __shfl_xor_sync(0xffffffffu, m0n, 2));
        m1n = fmaxf(m1n, __shfl_xor_sync(0xffffffffu, m1n, 1));
        m1n = fmaxf(m1n, __shfl_xor_sync(0xffffffffu, m1n, 2));

        const float al0 = __expf(m0 - m0n);
        const float al1 = __expf(m1 - m1n);

        float s0 = 0.f, s1 = 0.f;
        #pragma unroll
        for (int n = 0; n < 4; n++)
            #pragma unroll
            for (int t = 0; t < 8; t++) {
                float p = __expf(sacc[n].x[t] - ((t & 2) ? m1n : m0n));
                sacc[n].x[t] = p;
                if (t & 2) s1 += p; else s0 += p;
            }
        s0 += __shfl_xor_sync(0xffffffffu, s0, 1);
        s0 += __shfl_xor_sync(0xffffffffu, s0, 2);
        s1 += __shfl_xor_sync(0xffffffffu, s1, 1);
        s1 += __shfl_xor_sync(0xffffffffu, s1, 2);

        m0 = m0n; m1 = m1n;
        l0 = l0 * al0 + s0;
        l1 = l1 * al1 + s1;

        #pragma unroll
        for (int n = 0; n < 4; n++)
            #pragma unroll
            for (int t = 0; t < 8; t++)
                oacc[n].x[t] *= (t & 2) ? al1 : al0;

        // convert P to tf32, store to this warp's private band
        #pragma unroll
        for (int n = 0; n < 4; n++) {
            #pragma unroll
            for (int t = 0; t < 8; t++)
                sacc[n].x[t] = wmma::__float_to_tf32(sacc[n].x[t]);
            wmma::store_matrix_sync(Ps + warp_row0 * LDP + n * 16, sacc[n],
                                    LDP, wmma::mem_row_major);
        }

        __syncthreads();  // S2: all warps finished PV[j-1]'s V reads
        if (j + 1 < nkv) { issueV(j + 1, cur ^ 1); cp_commit(); }
    }

    cp_wait<0>();
    __syncthreads();
    do_pv(nkv - 1);

    // epilogue: O /= l, convert to tf32 bits, store
    const float rl0 = 1.f / l0;
    const float rl1 = 1.f / l1;
    float* ob = O + ((size_t)b * Sseq + (size_t)qt * 64 + warp_row0) * Eemb + h * Dd;
    #pragma unroll
    for (int n = 0; n < 4; n++) {
        #pragma unroll
        for (int t = 0; t < 8; t++)
            oacc[n].x[t] = wmma::__float_to_tf32(oacc[n].x[t] * ((t & 2) ? rl1 : rl0));
        wmma::store_matrix_sync(ob + n * 16, oacc[n], Eemb, wmma::mem_row_major);
    }
}

// ---------------------------------------------------------------------------
extern "C" void kernel_launch(void* const* d_in, const int* in_sizes, int n_in,
                              void* d_out, int out_size)
{
    const float* q   = (const float*)d_in[0];
    const float* k   = (const float*)d_in[1];
    const float* v   = (const float*)d_in[2];
    const float* w_q = (const float*)d_in[3];
    const float* b_q = (const float*)d_in[4];
    const float* w_k = (const float*)d_in[5];
    const float* b_k = (const float*)d_in[6];
    const float* w_v = (const float*)d_in[7];
    const float* b_v = (const float*)d_in[8];
    const float* w_o = (const float*)d_in[9];
    const float* b_o = (const float*)d_in[10];
    float* out = (float*)d_out;

    float *gq, *gk, *gv, *go, *cq, *ck, *cv, *wq, *wk, *wv, *wo;
    cudaGetSymbolAddress((void**)&gq, g_q);
    cudaGetSymbolAddress((void**)&gk, g_k);
    cudaGetSymbolAddress((void**)&gv, g_v);
    cudaGetSymbolAddress((void**)&go, g_o);
    cudaGetSymbolAddress((void**)&cq, g_cq);
    cudaGetSymbolAddress((void**)&ck, g_ck);
    cudaGetSymbolAddress((void**)&cv, g_cv);
    cudaGetSymbolAddress((void**)&wq, g_wq);
    cudaGetSymbolAddress((void**)&wk, g_wk);
    cudaGetSymbolAddress((void**)&wv, g_wv);
    cudaGetSymbolAddress((void**)&wo, g_wo);

    cudaFuncSetAttribute(gemm_bias_kernel,
                         cudaFuncAttributeMaxDynamicSharedMemorySize,
                         GEMM_SMEM_BYTES);
    cudaFuncSetAttribute(flash_kernel,
                         cudaFuncAttributeMaxDynamicSharedMemorySize,
                         FLASH_SMEM_BYTES);

    // 0) pre-convert inputs + weights to tf32 bits
    dim3 cvtGrid(1024, 7);
    cvt_tf32_kernel<<<cvtGrid, 256>>>(q, k, v, w_q, w_k, w_v, w_o,
                                      cq, ck, cv, wq, wk, wv, wo);

    // 1) fused QKV projections (tf32-bit outputs; K stored transposed)
    dim3 gGridQKV(Eemb / 128, Mrows / 128, 3);
    gemm_bias_kernel<<<gGridQKV, 256, GEMM_SMEM_BYTES>>>(
        cq, ck, cv, wq, wk, wv, b_q, b_k, b_v, gq, gk, gv, 1, 1);

    // 2) flash attention (K^T layout)
    dim3 fGrid(Sseq / 64, Bb * Hh);
    flash_kernel<<<fGrid, 128, FLASH_SMEM_BYTES>>>(gq, gk, gv, go);

    // 3) output projection (fp32 epilogue to d_out)
    dim3 gGridO(Eemb / 128, Mrows / 128, 1);
    gemm_bias_kernel<<<gGridO, 256, GEMM_SMEM_BYTES>>>(
        go, go, go, wo, wo, wo, b_o, b_o, b_o, out, out, out, 0, 0);
}

// round 15
// speedup vs baseline: 1.0766x; 1.0766x over previous
#include <cuda_runtime.h>
#include <cuda_bf16.h>
#include <mma.h>
#include <cstdint>

using namespace nvcuda;

// Problem constants
static constexpr int Bb   = 4;
static constexpr int Sseq = 2048;
static constexpr int Eemb = 1024;
static constexpr int Hh   = 16;
static constexpr int Dd   = 64;
static constexpr int Mrows = Bb * Sseq;   // 8192
static constexpr int NBIG  = Mrows * Eemb;   // 8388608
static constexpr int NWGT  = Eemb * Eemb;    // 1048576

// Scratch (device globals: allocation-free)
__device__ float g_q[(size_t)NBIG];    // Q proj (tf32 bits)
__device__ float g_k[(size_t)NBIG];    // K proj TRANSPOSED [b,h][d][s] (tf32)
__device__ float g_v[(size_t)NBIG];    // V proj (tf32 bits)
__device__ float g_o[(size_t)NBIG];    // attn out (tf32 bits)
__device__ float g_cq[(size_t)NBIG];   // input q (tf32 bits)
__device__ float g_ck[(size_t)NBIG];   // input k (tf32 bits)
__device__ float g_cv[(size_t)NBIG];   // input v (tf32 bits)
__device__ float g_wq[(size_t)NWGT];   // weights (tf32 bits)
__device__ float g_wk[(size_t)NWGT];
__device__ float g_wv[(size_t)NWGT];
__device__ float g_wo[(size_t)NWGT];

// ---------------------------------------------------------------------------
// cp.async helpers
// ---------------------------------------------------------------------------
__device__ __forceinline__ void cp_async16(void* smem, const void* gmem) {
    uint32_t s = (uint32_t)__cvta_generic_to_shared(smem);
    asm volatile("cp.async.cg.shared.global [%0], [%1], 16;\n" :: "r"(s), "l"(gmem));
}
__device__ __forceinline__ void cp_commit() {
    asm volatile("cp.async.commit_group;\n");
}
template<int N> __device__ __forceinline__ void cp_wait() {
    asm volatile("cp.async.wait_group %0;\n" :: "n"(N));
}

// ---------------------------------------------------------------------------
// Elementwise fp32 -> tf32-bits converter. grid.y selects array (0..6).
// ---------------------------------------------------------------------------
__global__ __launch_bounds__(256) void cvt_tf32_kernel(
    const float* __restrict__ s0, const float* __restrict__ s1,
    const float* __restrict__ s2, const float* __restrict__ s3,
    const float* __restrict__ s4, const float* __restrict__ s5,
    const float* __restrict__ s6,
    float* __restrict__ d0, float* __restrict__ d1, float* __restrict__ d2,
    float* __restrict__ d3, float* __restrict__ d4, float* __restrict__ d5,
    float* __restrict__ d6)
{
    const int y = blockIdx.y;
    const float* src; float* dst; int n;
    switch (y) {
        case 0: src = s0; dst = d0; n = NBIG; break;
        case 1: src = s1; dst = d1; n = NBIG; break;
        case 2: src = s2; dst = d2; n = NBIG; break;
        case 3: src = s3; dst = d3; n = NWGT; break;
        case 4: src = s4; dst = d4; n = NWGT; break;
        case 5: src = s5; dst = d5; n = NWGT; break;
        default: src = s6; dst = d6; n = NWGT; break;
    }
    const int stride = gridDim.x * blockDim.x * 4;
    for (int i = (blockIdx.x * blockDim.x + threadIdx.x) * 4; i < n; i += stride) {
        float4 v = *(const float4*)(src + i);
        v.x = wmma::__float_to_tf32(v.x);
        v.y = wmma::__float_to_tf32(v.y);
        v.z = wmma::__float_to_tf32(v.z);
        v.w = wmma::__float_to_tf32(v.w);
        *(float4*)(dst + i) = v;
    }
}

// ---------------------------------------------------------------------------
// GEMM: C[M,N] = A[M,K] @ W[K,N] + bias[N]  (M=8192, K=N=1024), tf32 wmma.
// REVERTED to the r13 shape that measured best: 128 threads, 4 warps of
// 64x64 (0.5 fragment loads per mma — the 64x32 experiment was 0.75 and
// regressed). Pre-converted tf32 operands -> zero cvt in mainloop.
// 3-stage cp.async ring, padded smem (LDA=36, LDB=132).
// z==1 && kT: store output TRANSPOSED per head ([b,h][d][s]) for flash.
// ---------------------------------------------------------------------------
static constexpr int GBM = 128, GBN = 128, GBK = 32;
static constexpr int LDA = 36;    // GBK + 4
static constexpr int LDB = 132;   // GBN + 4
static constexpr int GSTAGE = GBM * LDA + GBK * LDB;
static constexpr int GEMM_SMEM_BYTES = 3 * GSTAGE * (int)sizeof(float); // 105984

__global__ __launch_bounds__(128, 2) void gemm_bias_kernel(
    const float* __restrict__ A0, const float* __restrict__ A1,
    const float* __restrict__ A2,
    const float* __restrict__ W0, const float* __restrict__ W1,
    const float* __restrict__ W2,
    const float* __restrict__ bias0, const float* __restrict__ bias1,
    const float* __restrict__ bias2,
    float* __restrict__ C0, float* __restrict__ C1, float* __restrict__ C2,
    int cvt_out, int kT)
{
    constexpr int K = 1024, N = 1024;

    const int z = blockIdx.z;
    const float* A    = (z == 0) ? A0 : (z == 1) ? A1 : A2;
    const float* W    = (z == 0) ? W0 : (z == 1) ? W1 : W2;
    const float* bias = (z == 0) ? bias0 : (z == 1) ? bias1 : bias2;
    float*       C    = (z == 0) ? C0 : (z == 1) ? C1 : C2;
    const bool transK = (z == 1) && kT;

    extern __shared__ float smg[];

    const int tid  = threadIdx.x;
    const int lane = tid & 31;
    const int bm   = blockIdx.y * GBM;
    const int bn   = blockIdx.x * GBN;
    const int warp = tid >> 5;         // 0..3
    const int wr   = (warp >> 1) * 64;
    const int wc   = (warp & 1) * 64;

    auto issue_tile = [&](int kt, int buf) {
        const int k0 = kt * GBK;
        float* Ab = smg + buf * GSTAGE;
        float* Bbuf = Ab + GBM * LDA;
        #pragma unroll
        for (int t = 0; t < 8; t++) {
            int lin = tid + t * 128;
            int r = lin >> 3, c4 = lin & 7;
            cp_async16(Ab + r * LDA + c4 * 4,
                       A + (size_t)(bm + r) * K + k0 + c4 * 4);
        }
        #pragma unroll
        for (int t = 0; t < 8; t++) {
            int lin = tid + t * 128;
            int r = lin >> 5, c4 = lin & 31;
            cp_async16(Bbuf + r * LDB + c4 * 4,
                       W + (size_t)(k0 + r) * N + bn + c4 * 4);
        }
    };

    issue_tile(0, 0);
    cp_commit();
    issue_tile(1, 1);
    cp_commit();

    wmma::fragment<wmma::accumulator, 16, 16, 8, float> acc[4][4];
    #pragma unroll
    for (int i = 0; i < 4; i++)
        #pragma unroll
        for (int j = 0; j < 4; j++)
            wmma::fill_fragment(acc[i][j], 0.f);

    const int KT_ = K / GBK;  // 32
    int cur = 0;
    for (int kt = 0; kt < KT_; kt++) {
        if (kt + 1 < KT_) cp_wait<1>(); else cp_wait<0>();
        __syncthreads();
        if (kt + 2 < KT_) {
            int nb = cur + 2; if (nb >= 3) nb -= 3;
            issue_tile(kt + 2, nb);
            cp_commit();
        }

        const float* Ab = smg + cur * GSTAGE;
        const float* Bbuf = Ab + GBM * LDA;

        #pragma unroll
        for (int kk = 0; kk < GBK; kk += 8) {
            wmma::fragment<wmma::matrix_a, 16, 16, 8, wmma::precision::tf32,
                           wmma::row_major> af[4];
            #pragma unroll
            for (int i = 0; i < 4; i++)
                wmma::load_matrix_sync(af[i], Ab + (wr + i * 16) * LDA + kk, LDA);
            #pragma unroll
            for (int j = 0; j < 4; j++) {
                wmma::fragment<wmma::matrix_b, 16, 16, 8, wmma::precision::tf32,
                               wmma::row_major> bf;
                wmma::load_matrix_sync(bf, Bbuf + kk * LDB + wc + j * 16, LDB);
                #pragma unroll
                for (int i = 0; i < 4; i++)
                    wmma::mma_sync(acc[i][j], af[i], bf, acc[i][j]);
            }
        }
        cur++; if (cur == 3) cur = 0;
    }

    // epilogue
    #pragma unroll
    for (int j = 0; j < 4; j++) {
        const int colb = bn + wc + j * 16;
        const int col0 = colb + (lane & 3) * 2;
        float b0 = __ldg(bias + col0);
        float b1 = __ldg(bias + col0 + 1);
        float b8 = __ldg(bias + col0 + 8);
        float b9 = __ldg(bias + col0 + 9);
        #pragma unroll
        for (int i = 0; i < 4; i++) {
            acc[i][j].x[0] += b0; acc[i][j].x[1] += b1;
            acc[i][j].x[2] += b0; acc[i][j].x[3] += b1;
            acc[i][j].x[4] += b8; acc[i][j].x[5] += b9;
            acc[i][j].x[6] += b8; acc[i][j].x[7] += b9;
            if (cvt_out) {
                #pragma unroll
                for (int t = 0; t < 8; t++)
                    acc[i][j].x[t] = wmma::__float_to_tf32(acc[i][j].x[t]);
            }
            const int row0 = bm + wr + i * 16;
            if (transK) {
                // K^T store: (r,c) -> [(b,h)][d=colb%64+c][s=row0%2048+r]
                const int bIdx = row0 >> 11;
                const int s    = row0 & 2047;
                const int h    = colb >> 6;
                const int d    = colb & 63;
                float* dst = C + ((size_t)((bIdx << 4) + h) * 64 + d) * Sseq + s;
                wmma::store_matrix_sync(dst, acc[i][j], Sseq, wmma::mem_col_major);
            } else {
                wmma::store_matrix_sync(C + (size_t)row0 * N + colb,
                                        acc[i][j], N, wmma::mem_row_major);
            }
        }
    }
}

// ---------------------------------------------------------------------------
// Causal flash attention, tf32 wmma, Br=64, Bc=64, 4 warps (128 threads),
// software-pipelined (QK[j] -> PV[j-1] -> softmax[j]).
// K arrives TRANSPOSED ([b,h][d][s]) -> QK B-fragments are row_major,
// conflict-free. Q/K/V pre-converted tf32; P converts before store;
// O written as tf32 bits. smem = 104 KB -> 2 CTAs/SM.
// ---------------------------------------------------------------------------
static constexpr int LDP = 68;
static constexpr int KVTILE = 64 * LDP;
static constexpr int FLASH_SMEM_BYTES =
    (6 * KVTILE) * (int)sizeof(float);         // 104448

__global__ __launch_bounds__(128, 2) void flash_kernel(
    const float* __restrict__ Q, const float* __restrict__ KT,
    const float* __restrict__ V, float* __restrict__ O)
{
    extern __shared__ float sm[];
    float* Qs = sm;
    float* Ks = Qs + KVTILE;           // [2]  (K^T tiles: row = d, col = key)
    float* Vs = Ks + 2 * KVTILE;       // [2]
    float* Ps = Vs + 2 * KVTILE;       // per-warp private 16-row bands

    const int tid  = threadIdx.x;
    const int warp = tid >> 5;
    const int lane = tid & 31;
    const int qt   = (Sseq / 64 - 1) - blockIdx.x;
    const int bh   = blockIdx.y;
    const int b    = bh >> 4;
    const int h    = bh & 15;
    const float scale = 0.125f;        // 1/sqrt(64), power of 2

    const float* qb  = Q + ((size_t)b * Sseq + (size_t)qt * 64) * Eemb + h * Dd;
    const float* kTb = KT + (size_t)bh * 64 * Sseq;   // [d][s]
    const float* vb  = V + (size_t)b * Sseq * Eemb + h * Dd;

    auto issueK = [&](int j, int buf) {
        float* Kd = Ks + buf * KVTILE;
        const float* kt = kTb + (size_t)j * 64;   // col offset
        #pragma unroll
        for (int t = 0; t < 8; t++) {
            int lin = tid + t * 128;
            int r = lin >> 4, c4 = lin & 15;      // r = d row, c4*4 = key col
            cp_async16(Kd + r * LDP + c4 * 4, kt + (size_t)r * Sseq + c4 * 4);
        }
    };
    auto issueV = [&](int j, int buf) {
        const float* vt = vb + (size_t)j * 64 * Eemb;
        float* Vd = Vs + buf * KVTILE;
        #pragma unroll
        for (int t = 0; t < 8; t++) {
            int lin = tid + t * 128;
            int r = lin >> 4, c4 = lin & 15;
            cp_async16(Vd + r * LDP + c4 * 4, vt + (size_t)r * Eemb + c4 * 4);
        }
    };

    issueK(0, 0); cp_commit();
    issueV(0, 0); cp_commit();

    // Q tile: already tf32 bits; scale by 2^-3 (exact)
    #pragma unroll
    for (int t = 0; t < 8; t++) {
        int lin = tid + t * 128;
        int r = lin >> 4, c4 = lin & 15;
        float4 v4 = *(const float4*)(qb + (size_t)r * Eemb + c4 * 4);
        v4.x *= scale; v4.y *= scale; v4.z *= scale; v4.w *= scale;
        *(float4*)(Qs + r * LDP + c4 * 4) = v4;
    }

    float m0 = -1e30f, m1 = -1e30f, l0 = 0.f, l1 = 0.f;

    wmma::fragment<wmma::accumulator, 16, 16, 8, float> oacc[4];
    #pragma unroll
    for (int n = 0; n < 4; n++) wmma::fill_fragment(oacc[n], 0.f);

    const int warp_row0 = warp * 16;
    const int lr0 = warp_row0 + (lane >> 2);
    const int lr1 = lr0 + 8;
    const int nkv = qt + 1;

    auto do_pv = [&](int jj) {
        const float* Vc = Vs + (jj & 1) * KVTILE;
        #pragma unroll
        for (int kk = 0; kk < 64; kk += 8) {
            wmma::fragment<wmma::matrix_a, 16, 16, 8, wmma::precision::tf32,
                           wmma::row_major> af;
            wmma::load_matrix_sync(af, Ps + warp_row0 * LDP + kk, LDP);
            #pragma unroll
            for (int n = 0; n < 4; n++) {
                wmma::fragment<wmma::matrix_b, 16, 16, 8, wmma::precision::tf32,
                               wmma::row_major> bf;
                wmma::load_matrix_sync(bf, Vc + kk * LDP + n * 16, LDP);
                wmma::mma_sync(oacc[n], af, bf, oacc[n]);
            }
        }
    };

    for (int j = 0; j < nkv; j++) {
        const int cur = j & 1;

        cp_wait<1>();
        __syncthreads();  // S1: K[cur] visible; K[cur^1] free
        if (j + 1 < nkv) { issueK(j + 1, cur ^ 1); cp_commit(); }

        // ---- QK[j] ----  B = K^T tile, row_major (rows = d)
        const float* Kc = Ks + cur * KVTILE;
        wmma::fragment<wmma::accumulator, 16, 16, 8, float> sacc[4];
        #pragma unroll
        for (int n = 0; n < 4; n++) wmma::fill_fragment(sacc[n], 0.f);
        #pragma unroll
        for (int kk = 0; kk < 64; kk += 8) {
            wmma::fragment<wmma::matrix_a, 16, 16, 8, wmma::precision::tf32,
                           wmma::row_major> af;
            wmma::load_matrix_sync(af, Qs + warp_row0 * LDP + kk, LDP);
            #pragma unroll
            for (int n = 0; n < 4; n++) {
                wmma::fragment<wmma::matrix_b, 16, 16, 8, wmma::precision::tf32,
                               wmma::row_major> bf;
                wmma::load_matrix_sync(bf, Kc + kk * LDP + n * 16, LDP);
                wmma::mma_sync(sacc[n], af, bf, sacc[n]);
            }
        }

        // ---- PV[j-1] (drains under softmax[j]) ----
        if (j > 0) do_pv(j - 1);

        // ---- softmax[j] ----
        if (j == qt) {
            #pragma unroll
            for (int n = 0; n < 4; n++)
                #pragma unroll
                for (int t = 0; t < 8; t++) {
                    int c  = n * 16 + (lane & 3) * 2 + (t & 1) + ((t & 4) ? 8 : 0);
                    int lr = (t & 2) ? lr1 : lr0;
                    if (c > lr) sacc[n].x[t] = -1e30f;
                }
        }

        float m0n = m0, m1n = m1;
        #pragma unroll
        for (int n = 0; n < 4; n++)
            #pragma unroll
            for (int t = 0; t < 8; t++) {
                if (t & 2) m1n = fmaxf(m1n, sacc[n].x[t]);
                else       m0n = fmaxf(m0n, sacc[n].x[t]);
            }
        m0n = fmaxf(m0n, __shfl_xor_sync(0xffffffffu, m0n, 1));
        m0n = fmaxf(m0n, __shfl_xor_sync(0xffffffffu, m0n, 2));
        m1n = fmaxf(m1n, __shfl_xor_sync(0xffffffffu, m1n, 1));
        m1n = fmaxf(m1n, __shfl_xor_sync(0xffffffffu, m1n, 2));

        const float al0 = __expf(m0 - m0n);
        const float al1 = __expf(m1 - m1n);

        float s0 = 0.f, s1 = 0.f;
        #pragma unroll
        for (int n = 0; n < 4; n++)
            #pragma unroll
            for (int t = 0; t < 8; t++) {
                float p = __expf(sacc[n].x[t] - ((t & 2) ? m1n : m0n));
                sacc[n].x[t] = p;
                if (t & 2) s1 += p; else s0 += p;
            }
        s0 += __shfl_xor_sync(0xffffffffu, s0, 1);
        s0 += __shfl_xor_sync(0xffffffffu, s0, 2);
        s1 += __shfl_xor_sync(0xffffffffu, s1, 1);
        s1 += __shfl_xor_sync(0xffffffffu, s1, 2);

        m0 = m0n; m1 = m1n;
        l0 = l0 * al0 + s0;
        l1 = l1 * al1 + s1;

        #pragma unroll
        for (int n = 0; n < 4; n++)
            #pragma unroll
            for (int t = 0; t < 8; t++)
                oacc[n].x[t] *= (t & 2) ? al1 : al0;

        // convert P to tf32, store to this warp's private band
        #pragma unroll
        for (int n = 0; n < 4; n++) {
            #pragma unroll
            for (int t = 0; t < 8; t++)
                sacc[n].x[t] = wmma::__float_to_tf32(sacc[n].x[t]);
            wmma::store_matrix_sync(Ps + warp_row0 * LDP + n * 16, sacc[n],
                                    LDP, wmma::mem_row_major);
        }

        __syncthreads();  // S2: all warps finished PV[j-1]'s V reads
        if (j + 1 < nkv) { issueV(j + 1, cur ^ 1); cp_commit(); }
    }

    cp_wait<0>();
    __syncthreads();
    do_pv(nkv - 1);

    // epilogue: O /= l, convert to tf32 bits, store
    const float rl0 = 1.f / l0;
    const float rl1 = 1.f / l1;
    float* ob = O + ((size_t)b * Sseq + (size_t)qt * 64 + warp_row0) * Eemb + h * Dd;
    #pragma unroll
    for (int n = 0; n < 4; n++) {
        #pragma unroll
        for (int t = 0; t < 8; t++)
            oacc[n].x[t] = wmma::__float_to_tf32(oacc[n].x[t] * ((t & 2) ? rl1 : rl0));
        wmma::store_matrix_sync(ob + n * 16, oacc[n], Eemb, wmma::mem_row_major);
    }
}

// ---------------------------------------------------------------------------
extern "C" void kernel_launch(void* const* d_in, const int* in_sizes, int n_in,
                              void* d_out, int out_size)
{
    const float* q   = (const float*)d_in[0];
    const float* k   = (const float*)d_in[1];
    const float* v   = (const float*)d_in[2];
    const float* w_q = (const float*)d_in[3];
    const float* b_q = (const float*)d_in[4];
    const float* w_k = (const float*)d_in[5];
    const float* b_k = (const float*)d_in[6];
    const float* w_v = (const float*)d_in[7];
    const float* b_v = (const float*)d_in[8];
    const float* w_o = (const float*)d_in[9];
    const float* b_o = (const float*)d_in[10];
    float* out = (float*)d_out;

    float *gq, *gk, *gv, *go, *cq, *ck, *cv, *wq, *wk, *wv, *wo;
    cudaGetSymbolAddress((void**)&gq, g_q);
    cudaGetSymbolAddress((void**)&gk, g_k);
    cudaGetSymbolAddress((void**)&gv, g_v);
    cudaGetSymbolAddress((void**)&go, g_o);
    cudaGetSymbolAddress((void**)&cq, g_cq);
    cudaGetSymbolAddress((void**)&ck, g_ck);
    cudaGetSymbolAddress((void**)&cv, g_cv);
    cudaGetSymbolAddress((void**)&wq, g_wq);
    cudaGetSymbolAddress((void**)&wk, g_wk);
    cudaGetSymbolAddress((void**)&wv, g_wv);
    cudaGetSymbolAddress((void**)&wo, g_wo);

    cudaFuncSetAttribute(gemm_bias_kernel,
                         cudaFuncAttributeMaxDynamicSharedMemorySize,
                         GEMM_SMEM_BYTES);
    cudaFuncSetAttribute(flash_kernel,
                         cudaFuncAttributeMaxDynamicSharedMemorySize,
                         FLASH_SMEM_BYTES);

    // 0) pre-convert inputs + weights to tf32 bits
    dim3 cvtGrid(1024, 7);
    cvt_tf32_kernel<<<cvtGrid, 256>>>(q, k, v, w_q, w_k, w_v, w_o,
                                      cq, ck, cv, wq, wk, wv, wo);

    // 1) fused QKV projections (tf32-bit outputs; K stored transposed)
    dim3 gGridQKV(Eemb / 128, Mrows / 128, 3);
    gemm_bias_kernel<<<gGridQKV, 128, GEMM_SMEM_BYTES>>>(
        cq, ck, cv, wq, wk, wv, b_q, b_k, b_v, gq, gk, gv, 1, 1);

    // 2) flash attention (K^T layout)
    dim3 fGrid(Sseq / 64, Bb * Hh);
    flash_kernel<<<fGrid, 128, FLASH_SMEM_BYTES>>>(gq, gk, gv, go);

    // 3) output projection (fp32 epilogue to d_out)
    dim3 gGridO(Eemb / 128, Mrows / 128, 1);
    gemm_bias_kernel<<<gGridO, 128, GEMM_SMEM_BYTES>>>(
        go, go, go, wo, wo, wo, b_o, b_o, b_o, out, out, out, 0, 0);
}

// round 16
// speedup vs baseline: 1.0868x; 1.0095x over previous
#include <cuda_runtime.h>
#include <cuda_bf16.h>
#include <mma.h>
#include <cstdint>

using namespace nvcuda;

// Problem constants
static constexpr int Bb   = 4;
static constexpr int Sseq = 2048;
static constexpr int Eemb = 1024;
static constexpr int Hh   = 16;
static constexpr int Dd   = 64;
static constexpr int Mrows = Bb * Sseq;   // 8192
static constexpr int NBIG  = Mrows * Eemb;   // 8388608
static constexpr int NWGT  = Eemb * Eemb;    // 1048576

// Scratch (device globals: allocation-free)
__device__ float g_q[(size_t)NBIG];    // Q proj (tf32 bits)
__device__ float g_k[(size_t)NBIG];    // K proj (tf32 bits)
__device__ float g_v[(size_t)NBIG];    // V proj (tf32 bits)
__device__ float g_o[(size_t)NBIG];    // attn out (tf32 bits)
__device__ float g_cq[(size_t)NBIG];   // input q (tf32 bits)
__device__ float g_ck[(size_t)NBIG];   // input k (tf32 bits)
__device__ float g_cv[(size_t)NBIG];   // input v (tf32 bits)
__device__ float g_wq[(size_t)NWGT];   // weights (tf32 bits)
__device__ float g_wk[(size_t)NWGT];
__device__ float g_wv[(size_t)NWGT];
__device__ float g_wo[(size_t)NWGT];

// ---------------------------------------------------------------------------
// cp.async helpers
// ---------------------------------------------------------------------------
__device__ __forceinline__ void cp_async16(void* smem, const void* gmem) {
    uint32_t s = (uint32_t)__cvta_generic_to_shared(smem);
    asm volatile("cp.async.cg.shared.global [%0], [%1], 16;\n" :: "r"(s), "l"(gmem));
}
__device__ __forceinline__ void cp_commit() {
    asm volatile("cp.async.commit_group;\n");
}
template<int N> __device__ __forceinline__ void cp_wait() {
    asm volatile("cp.async.wait_group %0;\n" :: "n"(N));
}

// ---------------------------------------------------------------------------
// Elementwise fp32 -> tf32-bits converter. grid.y selects array (0..6).
// ---------------------------------------------------------------------------
__global__ __launch_bounds__(256) void cvt_tf32_kernel(
    const float* __restrict__ s0, const float* __restrict__ s1,
    const float* __restrict__ s2, const float* __restrict__ s3,
    const float* __restrict__ s4, const float* __restrict__ s5,
    const float* __restrict__ s6,
    float* __restrict__ d0, float* __restrict__ d1, float* __restrict__ d2,
    float* __restrict__ d3, float* __restrict__ d4, float* __restrict__ d5,
    float* __restrict__ d6)
{
    const int y = blockIdx.y;
    const float* src; float* dst; int n;
    switch (y) {
        case 0: src = s0; dst = d0; n = NBIG; break;
        case 1: src = s1; dst = d1; n = NBIG; break;
        case 2: src = s2; dst = d2; n = NBIG; break;
        case 3: src = s3; dst = d3; n = NWGT; break;
        case 4: src = s4; dst = d4; n = NWGT; break;
        case 5: src = s5; dst = d5; n = NWGT; break;
        default: src = s6; dst = d6; n = NWGT; break;
    }
    const int stride = gridDim.x * blockDim.x * 4;
    for (int i = (blockIdx.x * blockDim.x + threadIdx.x) * 4; i < n; i += stride) {
        float4 v = *(const float4*)(src + i);
        v.x = wmma::__float_to_tf32(v.x);
        v.y = wmma::__float_to_tf32(v.y);
        v.z = wmma::__float_to_tf32(v.z);
        v.w = wmma::__float_to_tf32(v.w);
        *(float4*)(dst + i) = v;
    }
}

// ---------------------------------------------------------------------------
// GEMM: C[M,N] = A[M,K] @ W[K,N] + bias[N]  (M=8192, K=N=1024), tf32 wmma.
// r13 shape (best measured): 128 threads, 4 warps of 64x64, pre-converted
// tf32 operands, 3-stage cp.async ring, padded smem (LDA=36, LDB=132).
// ---------------------------------------------------------------------------
static constexpr int GBM = 128, GBN = 128, GBK = 32;
static constexpr int LDA = 36;    // GBK + 4
static constexpr int LDB = 132;   // GBN + 4
static constexpr int GSTAGE = GBM * LDA + GBK * LDB;
static constexpr int GEMM_SMEM_BYTES = 3 * GSTAGE * (int)sizeof(float); // 105984

__global__ __launch_bounds__(128, 2) void gemm_bias_kernel(
    const float* __restrict__ A0, const float* __restrict__ A1,
    const float* __restrict__ A2,
    const float* __restrict__ W0, const float* __restrict__ W1,
    const float* __restrict__ W2,
    const float* __restrict__ bias0, const float* __restrict__ bias1,
    const float* __restrict__ bias2,
    float* __restrict__ C0, float* __restrict__ C1, float* __restrict__ C2,
    int cvt_out)
{
    constexpr int K = 1024, N = 1024;

    const int z = blockIdx.z;
    const float* A    = (z == 0) ? A0 : (z == 1) ? A1 : A2;
    const float* W    = (z == 0) ? W0 : (z == 1) ? W1 : W2;
    const float* bias = (z == 0) ? bias0 : (z == 1) ? bias1 : bias2;
    float*       C    = (z == 0) ? C0 : (z == 1) ? C1 : C2;

    extern __shared__ float smg[];

    const int tid  = threadIdx.x;
    const int lane = tid & 31;
    const int bm   = blockIdx.y * GBM;
    const int bn   = blockIdx.x * GBN;
    const int warp = tid >> 5;         // 0..3
    const int wr   = (warp >> 1) * 64;
    const int wc   = (warp & 1) * 64;

    auto issue_tile = [&](int kt, int buf) {
        const int k0 = kt * GBK;
        float* Ab = smg + buf * GSTAGE;
        float* Bbuf = Ab + GBM * LDA;
        #pragma unroll
        for (int t = 0; t < 8; t++) {
            int lin = tid + t * 128;
            int r = lin >> 3, c4 = lin & 7;
            cp_async16(Ab + r * LDA + c4 * 4,
                       A + (size_t)(bm + r) * K + k0 + c4 * 4);
        }
        #pragma unroll
        for (int t = 0; t < 8; t++) {
            int lin = tid + t * 128;
            int r = lin >> 5, c4 = lin & 31;
            cp_async16(Bbuf + r * LDB + c4 * 4,
                       W + (size_t)(k0 + r) * N + bn + c4 * 4);
        }
    };

    issue_tile(0, 0);
    cp_commit();
    issue_tile(1, 1);
    cp_commit();

    wmma::fragment<wmma::accumulator, 16, 16, 8, float> acc[4][4];
    #pragma unroll
    for (int i = 0; i < 4; i++)
        #pragma unroll
        for (int j = 0; j < 4; j++)
            wmma::fill_fragment(acc[i][j], 0.f);

    const int KT_ = K / GBK;  // 32
    int cur = 0;
    for (int kt = 0; kt < KT_; kt++) {
        if (kt + 1 < KT_) cp_wait<1>(); else cp_wait<0>();
        __syncthreads();
        if (kt + 2 < KT_) {
            int nb = cur + 2; if (nb >= 3) nb -= 3;
            issue_tile(kt + 2, nb);
            cp_commit();
        }

        const float* Ab = smg + cur * GSTAGE;
        const float* Bbuf = Ab + GBM * LDA;

        #pragma unroll
        for (int kk = 0; kk < GBK; kk += 8) {
            wmma::fragment<wmma::matrix_a, 16, 16, 8, wmma::precision::tf32,
                           wmma::row_major> af[4];
            #pragma unroll
            for (int i = 0; i < 4; i++)
                wmma::load_matrix_sync(af[i], Ab + (wr + i * 16) * LDA + kk, LDA);
            #pragma unroll
            for (int j = 0; j < 4; j++) {
                wmma::fragment<wmma::matrix_b, 16, 16, 8, wmma::precision::tf32,
                               wmma::row_major> bf;
                wmma::load_matrix_sync(bf, Bbuf + kk * LDB + wc + j * 16, LDB);
                #pragma unroll
                for (int i = 0; i < 4; i++)
                    wmma::mma_sync(acc[i][j], af[i], bf, acc[i][j]);
            }
        }
        cur++; if (cur == 3) cur = 0;
    }

    // epilogue: + bias (fp32); optionally convert to tf32 bits; store
    #pragma unroll
    for (int j = 0; j < 4; j++) {
        const int colb = bn + wc + j * 16;
        const int col0 = colb + (lane & 3) * 2;
        float b0 = __ldg(bias + col0);
        float b1 = __ldg(bias + col0 + 1);
        float b8 = __ldg(bias + col0 + 8);
        float b9 = __ldg(bias + col0 + 9);
        #pragma unroll
        for (int i = 0; i < 4; i++) {
            acc[i][j].x[0] += b0; acc[i][j].x[1] += b1;
            acc[i][j].x[2] += b0; acc[i][j].x[3] += b1;
            acc[i][j].x[4] += b8; acc[i][j].x[5] += b9;
            acc[i][j].x[6] += b8; acc[i][j].x[7] += b9;
            if (cvt_out) {
                #pragma unroll
                for (int t = 0; t < 8; t++)
                    acc[i][j].x[t] = wmma::__float_to_tf32(acc[i][j].x[t]);
            }
            wmma::store_matrix_sync(C + (size_t)(bm + wr + i * 16) * N + colb,
                                    acc[i][j], N, wmma::mem_row_major);
        }
    }
}

// ---------------------------------------------------------------------------
// Causal flash attention, tf32 wmma, Br=64, Bc=64, 4 warps (128 threads),
// software-pipelined (QK[j] -> PV[j-1] -> softmax[j]).
// NEW vs r13:
//  * Q lives in 8 persistent A-fragments (loaded once from gmem, x0.125
//    exact) -> no Qs smem tile, no QK A-fragment LDS per iteration.
//  * V triple-buffered ring: writer (j+1)%3 never collides with PV[j-1]'s
//    reader (j-1)%3 -> the second block barrier is GONE. ONE
//    __syncthreads per iteration; K+V prefetch in one commit group at S1.
//  * no trailing barrier (own-warp Ps, V already waited).
// smem = 2K + 3V + P = 6 tiles = 104 KB -> 2 CTAs/SM.
// ---------------------------------------------------------------------------
static constexpr int LDP = 68;
static constexpr int KVTILE = 64 * LDP;
static constexpr int FLASH_SMEM_BYTES =
    (6 * KVTILE) * (int)sizeof(float);         // 104448

__global__ __launch_bounds__(128, 2) void flash_kernel(
    const float* __restrict__ Q, const float* __restrict__ Kg,
    const float* __restrict__ V, float* __restrict__ O)
{
    extern __shared__ float sm[];
    float* Ks = sm;                    // [2] 64x68
    float* Vs = Ks + 2 * KVTILE;       // [3] 64x68
    float* Ps = Vs + 3 * KVTILE;       // per-warp private 16-row bands

    const int tid  = threadIdx.x;
    const int warp = tid >> 5;
    const int lane = tid & 31;
    const int qt   = (Sseq / 64 - 1) - blockIdx.x;   // heavy tiles first
    const int bh   = blockIdx.y;
    const int b    = bh >> 4;
    const int h    = bh & 15;

    const float* qb = Q + ((size_t)b * Sseq + (size_t)qt * 64) * Eemb + h * Dd;
    const float* kb = Kg + (size_t)b * Sseq * Eemb + h * Dd;
    const float* vb = V + (size_t)b * Sseq * Eemb + h * Dd;

    const int warp_row0 = warp * 16;
    const int lr0 = warp_row0 + (lane >> 2);
    const int lr1 = lr0 + 8;
    const int nkv = qt + 1;

    // prefetch KV tile j: K -> Ks[j&1], V -> Vs[j%3], one commit group
    auto issueKV = [&](int j) {
        const float* kt = kb + (size_t)j * 64 * Eemb;
        const float* vt = vb + (size_t)j * 64 * Eemb;
        float* Kd = Ks + (j & 1) * KVTILE;
        float* Vd = Vs + (j % 3) * KVTILE;
        #pragma unroll
        for (int t = 0; t < 8; t++) {
            int lin = tid + t * 128;
            int r = lin >> 4, c4 = lin & 15;
            cp_async16(Kd + r * LDP + c4 * 4, kt + (size_t)r * Eemb + c4 * 4);
            cp_async16(Vd + r * LDP + c4 * 4, vt + (size_t)r * Eemb + c4 * 4);
        }
        cp_commit();
    };

    issueKV(0);

    // Q: 8 persistent A-fragments straight from gmem (tf32 bits), x0.125 exact
    wmma::fragment<wmma::matrix_a, 16, 16, 8, wmma::precision::tf32,
                   wmma::row_major> qf[8];
    #pragma unroll
    for (int i = 0; i < 8; i++) {
        wmma::load_matrix_sync(qf[i], qb + (size_t)warp_row0 * Eemb + i * 8, Eemb);
        #pragma unroll
        for (int t = 0; t < qf[i].num_elements; t++)
            qf[i].x[t] *= 0.125f;
    }

    float m0 = -1e30f, m1 = -1e30f, l0 = 0.f, l1 = 0.f;

    wmma::fragment<wmma::accumulator, 16, 16, 8, float> oacc[4];
    #pragma unroll
    for (int n = 0; n < 4; n++) wmma::fill_fragment(oacc[n], 0.f);

    auto do_pv = [&](int jj) {
        const float* Vc = Vs + (jj % 3) * KVTILE;
        #pragma unroll
        for (int kk = 0; kk < 64; kk += 8) {
            wmma::fragment<wmma::matrix_a, 16, 16, 8, wmma::precision::tf32,
                           wmma::row_major> af;
            wmma::load_matrix_sync(af, Ps + warp_row0 * LDP + kk, LDP);
            #pragma unroll
            for (int n = 0; n < 4; n++) {
                wmma::fragment<wmma::matrix_b, 16, 16, 8, wmma::precision::tf32,
                               wmma::row_major> bf;
                wmma::load_matrix_sync(bf, Vc + kk * LDP + n * 16, LDP);
                wmma::mma_sync(oacc[n], af, bf, oacc[n]);
            }
        }
    };

    for (int j = 0; j < nkv; j++) {
        cp_wait<0>();
        __syncthreads();  // S1 (the ONLY barrier): KV[j] visible; every warp
                          // finished iter j-1 -> K[(j+1)&1], V[(j+1)%3] free
        if (j + 1 < nkv) issueKV(j + 1);

        // ---- QK[j] ---- (A-operands resident in registers)
        const float* Kc = Ks + (j & 1) * KVTILE;
        wmma::fragment<wmma::accumulator, 16, 16, 8, float> sacc[4];
        #pragma unroll
        for (int n = 0; n < 4; n++) wmma::fill_fragment(sacc[n], 0.f);
        #pragma unroll
        for (int kk = 0; kk < 64; kk += 8) {
            #pragma unroll
            for (int n = 0; n < 4; n++) {
                wmma::fragment<wmma::matrix_b, 16, 16, 8, wmma::precision::tf32,
                               wmma::col_major> bf;
                wmma::load_matrix_sync(bf, Kc + (n * 16) * LDP + kk, LDP);
                wmma::mma_sync(sacc[n], qf[kk >> 3], bf, sacc[n]);
            }
        }

        // ---- PV[j-1] (drains under softmax[j]) ----
        if (j > 0) do_pv(j - 1);

        // ---- softmax[j] ----
        if (j == qt) {
            #pragma unroll
            for (int n = 0; n < 4; n++)
                #pragma unroll
                for (int t = 0; t < 8; t++) {
                    int c  = n * 16 + (lane & 3) * 2 + (t & 1) + ((t & 4) ? 8 : 0);
                    int lr = (t & 2) ? lr1 : lr0;
                    if (c > lr) sacc[n].x[t] = -1e30f;
                }
        }

        float m0n = m0, m1n = m1;
        #pragma unroll
        for (int n = 0; n < 4; n++)
            #pragma unroll
            for (int t = 0; t < 8; t++) {
                if (t & 2) m1n = fmaxf(m1n, sacc[n].x[t]);
                else       m0n = fmaxf(m0n, sacc[n].x[t]);
            }
        m0n = fmaxf(m0n, __shfl_xor_sync(0xffffffffu, m0n, 1));
        m0n = fmaxf(m0n, __shfl_xor_sync(0xffffffffu, m0n, 2));
        m1n = fmaxf(m1n, __shfl_xor_sync(0xffffffffu, m1n, 1));
        m1n = fmaxf(m1n, __shfl_xor_sync(0xffffffffu, m1n, 2));

        const float al0 = __expf(m0 - m0n);
        const float al1 = __expf(m1 - m1n);

        float s0 = 0.f, s1 = 0.f;
        #pragma unroll
        for (int n = 0; n < 4; n++)
            #pragma unroll
            for (int t = 0; t < 8; t++) {
                float p = __expf(sacc[n].x[t] - ((t & 2) ? m1n : m0n));
                sacc[n].x[t] = p;
                if (t & 2) s1 += p; else s0 += p;
            }
        s0 += __shfl_xor_sync(0xffffffffu, s0, 1);
        s0 += __shfl_xor_sync(0xffffffffu, s0, 2);
        s1 += __shfl_xor_sync(0xffffffffu, s1, 1);
        s1 += __shfl_xor_sync(0xffffffffu, s1, 2);

        m0 = m0n; m1 = m1n;
        l0 = l0 * al0 + s0;
        l1 = l1 * al1 + s1;

        // rescale O (ordered after PV[j-1] via oacc scoreboard)
        #pragma unroll
        for (int n = 0; n < 4; n++)
            #pragma unroll
            for (int t = 0; t < 8; t++)
                oacc[n].x[t] *= (t & 2) ? al1 : al0;

        // convert P to tf32, store to this warp's PRIVATE band
        #pragma unroll
        for (int n = 0; n < 4; n++) {
            #pragma unroll
            for (int t = 0; t < 8; t++)
                sacc[n].x[t] = wmma::__float_to_tf32(sacc[n].x[t]);
            wmma::store_matrix_sync(Ps + warp_row0 * LDP + n * 16, sacc[n],
                                    LDP, wmma::mem_row_major);
        }
        __syncwarp();  // own-warp P store -> own-warp P load ordering
        // no second barrier: V writer (j+1)%3 != PV reader (j-1)%3
    }

    // trailing PV: V[nkv-1] already waited at its iteration; Ps own-warp
    do_pv(nkv - 1);

    // epilogue: O /= l, convert to tf32 bits, store
    const float rl0 = 1.f / l0;
    const float rl1 = 1.f / l1;
    float* ob = O + ((size_t)b * Sseq + (size_t)qt * 64 + warp_row0) * Eemb + h * Dd;
    #pragma unroll
    for (int n = 0; n < 4; n++) {
        #pragma unroll
        for (int t = 0; t < 8; t++)
            oacc[n].x[t] = wmma::__float_to_tf32(oacc[n].x[t] * ((t & 2) ? rl1 : rl0));
        wmma::store_matrix_sync(ob + n * 16, oacc[n], Eemb, wmma::mem_row_major);
    }
}

// ---------------------------------------------------------------------------
extern "C" void kernel_launch(void* const* d_in, const int* in_sizes, int n_in,
                              void* d_out, int out_size)
{
    const float* q   = (const float*)d_in[0];
    const float* k   = (const float*)d_in[1];
    const float* v   = (const float*)d_in[2];
    const float* w_q = (const float*)d_in[3];
    const float* b_q = (const float*)d_in[4];
    const float* w_k = (const float*)d_in[5];
    const float* b_k = (const float*)d_in[6];
    const float* w_v = (const float*)d_in[7];
    const float* b_v = (const float*)d_in[8];
    const float* w_o = (const float*)d_in[9];
    const float* b_o = (const float*)d_in[10];
    float* out = (float*)d_out;

    float *gq, *gk, *gv, *go, *cq, *ck, *cv, *wq, *wk, *wv, *wo;
    cudaGetSymbolAddress((void**)&gq, g_q);
    cudaGetSymbolAddress((void**)&gk, g_k);
    cudaGetSymbolAddress((void**)&gv, g_v);
    cudaGetSymbolAddress((void**)&go, g_o);
    cudaGetSymbolAddress((void**)&cq, g_cq);
    cudaGetSymbolAddress((void**)&ck, g_ck);
    cudaGetSymbolAddress((void**)&cv, g_cv);
    cudaGetSymbolAddress((void**)&wq, g_wq);
    cudaGetSymbolAddress((void**)&wk, g_wk);
    cudaGetSymbolAddress((void**)&wv, g_wv);
    cudaGetSymbolAddress((void**)&wo, g_wo);

    cudaFuncSetAttribute(gemm_bias_kernel,
                         cudaFuncAttributeMaxDynamicSharedMemorySize,
                         GEMM_SMEM_BYTES);
    cudaFuncSetAttribute(flash_kernel,
                         cudaFuncAttributeMaxDynamicSharedMemorySize,
                         FLASH_SMEM_BYTES);

    // 0) pre-convert inputs + weights to tf32 bits
    dim3 cvtGrid(1024, 7);
    cvt_tf32_kernel<<<cvtGrid, 256>>>(q, k, v, w_q, w_k, w_v, w_o,
                                      cq, ck, cv, wq, wk, wv, wo);

    // 1) fused QKV projections (tf32-bit outputs)
    dim3 gGridQKV(Eemb / 128, Mrows / 128, 3);
    gemm_bias_kernel<<<gGridQKV, 128, GEMM_SMEM_BYTES>>>(
        cq, ck, cv, wq, wk, wv, b_q, b_k, b_v, gq, gk, gv, 1);

    // 2) flash attention
    dim3 fGrid(Sseq / 64, Bb * Hh);
    flash_kernel<<<fGrid, 128, FLASH_SMEM_BYTES>>>(gq, gk, gv, go);

    // 3) output projection (fp32 epilogue to d_out)
    dim3 gGridO(Eemb / 128, Mrows / 128, 1);
    gemm_bias_kernel<<<gGridO, 128, GEMM_SMEM_BYTES>>>(
        go, go, go, wo, wo, wo, b_o, b_o, b_o, out, out, out, 0);
}